// round 7
// baseline (speedup 1.0000x reference)
#include <cuda_runtime.h>

#define S_TILE   16
#define KF       32
#define ROWS     48            // S_TILE + KF (ring buffer size)
#define CHAIN    4             // s-tiles per CTA
#define DCONST   1024
#define D4       256           // D / 4
#define PITCH4   257           // float4 pitch per row
#define COLS     48
#define NEG_BIG  -1.0e9f

#define TILE_F4      (ROWS * PITCH4)
#define RED_OFF      (TILE_F4 * 4)            // 49344
#define RED_SIZE     (8 * S_TILE * COLS)
#define W_OFF        (RED_OFF + RED_SIZE)     // 55488
#define SMEM_FLOATS  (W_OFF + S_TILE * COLS * 2)
#define SMEM_BYTES   (SMEM_FLOATS * 4)        // 228096 B

typedef unsigned long long u64;

__device__ __forceinline__ void fma2(u64& d, u64 a, u64 b) {
    asm("fma.rn.f32x2 %0, %1, %2, %0;" : "+l"(d) : "l"(a), "l"(b));
}
__device__ __forceinline__ float sum2(u64 a) {
    float2 v = *reinterpret_cast<float2*>(&a);
    return v.x + v.y;
}

__global__ __launch_bounds__(1024, 1)
void future_encoder_kernel(const float* __restrict__ in,
                           float* __restrict__ out,
                           int S)
{
    extern __shared__ float smem[];
    ulonglong2* tileU = reinterpret_cast<ulonglong2*>(smem);
    float4*     tile4 = reinterpret_cast<float4*>(smem);
    float*      red   = smem + RED_OFF;
    u64*        Wd    = reinterpret_cast<u64*>(smem + W_OFF);
    float2*     Wd2   = reinterpret_cast<float2*>(smem + W_OFF);

    const int tid   = threadIdx.x;
    const int chain = blockIdx.x;
    const int bb    = blockIdx.y;
    const int t0    = chain * CHAIN;

    const float4* in4  = reinterpret_cast<const float4*>(in)  + (size_t)bb * S * D4;
    float4*       out4 = reinterpret_cast<float4*>(out)       + (size_t)bb * S * D4;

    // ---- initial load: 48 rows x 256 f4, 12 f4 per thread, coalesced ----
    #pragma unroll
    for (int it = 0; it < 12; ++it) {
        const int idx = tid + it * 1024;
        const int r = idx >> 8;
        const int c = idx & 255;
        int gr = t0 * S_TILE + r;
        if (gr > S - 1) gr = S - 1;
        tile4[r * PITCH4 + c] = in4[(size_t)gr * D4 + c];
    }

    int rot = 0;

    for (int tt = 0; tt < CHAIN; ++tt) {
        const int s0 = (t0 + tt) * S_TILE;
        __syncthreads();   // tile (loads / refresh) visible

        // ===== Phase A (all 32 warps): warp=(d-group g, row-quarter h) =====
        // lane: one q-row (4h + lane>>3, broadcast) x 6 j-cols (lane&7 + 8jj)
        {
            const int w    = tid >> 5;
            const int lane = tid & 31;
            const int g    = w >> 2;          // d-group 0..7 (128 dims)
            const int h    = w & 3;           // row-quarter 0..3
            const int a    = lane >> 3;       // 0..3
            const int b    = lane & 7;        // 0..7
            const int base = g * 32;          // f4 col start

            int qr = 4 * h + a + rot; if (qr >= ROWS) qr -= ROWS;
            const int qs = qr * PITCH4;

            int fs[6];
            #pragma unroll
            for (int jj = 0; jj < 6; ++jj) {
                int r = b + 8 * jj + rot; if (r >= ROWS) r -= ROWS;
                fs[jj] = r * PITCH4;
            }

            u64 acc[6];
            #pragma unroll
            for (int jj = 0; jj < 6; ++jj) acc[jj] = 0ull;

            #pragma unroll 4
            for (int step = 0; step < 32; ++step) {
                const int col = base + step;
                const ulonglong2 q = tileU[qs + col];     // 4 rows x 16B: 1 wf
                #pragma unroll
                for (int jj = 0; jj < 6; ++jj) {
                    const ulonglong2 f = tileU[fs[jj] + col];  // 8 rows x 16B: 1 wf
                    fma2(acc[jj], q.x, f.x);
                    fma2(acc[jj], q.y, f.y);
                }
            }

            float* myred = red + g * (S_TILE * COLS) + (4 * h + a) * COLS + b;
            #pragma unroll
            for (int jj = 0; jj < 6; ++jj)
                myred[8 * jj] = sum2(acc[jj]);
        }
        __syncthreads();   // red complete

        // ===== concurrent: softmax (warps 0-15) || refresh LDG (warps 16-31) =====
        float4 st[8];
        if (tid < 512) {
            const int row  = tid >> 5;       // query row 0..15
            const int lane = tid & 31;

            float s1 = 0.0f, s2 = 0.0f;
            #pragma unroll
            for (int g = 0; g < 8; ++g)
                s1 += red[g * (S_TILE * COLS) + row * COLS + lane];
            if (lane < 16) {
                #pragma unroll
                for (int g = 0; g < 8; ++g)
                    s2 += red[g * (S_TILE * COLS) + row * COLS + 32 + lane];
            }

            const int j1 = lane;
            const int k1 = j1 - row - 1;
            const bool val1 = (k1 >= 0) && (k1 < KF) && (s0 + j1 < S);
            const float v1 = val1 ? s1 : NEG_BIG;

            const int j2 = 32 + lane;
            const int k2 = j2 - row - 1;
            const bool val2 = (lane < 16) && (k2 >= 0) && (k2 < KF) && (s0 + j2 < S);
            const float v2 = val2 ? s2 : NEG_BIG;

            float m = fmaxf(v1, v2);
            #pragma unroll
            for (int o = 16; o > 0; o >>= 1)
                m = fmaxf(m, __shfl_xor_sync(0xFFFFFFFFu, m, o));

            const float e1 = __expf(v1 - m);
            const float e2 = (lane < 16) ? __expf(v2 - m) : 0.0f;
            float sum = e1 + e2;
            #pragma unroll
            for (int o = 16; o > 0; o >>= 1)
                sum += __shfl_xor_sync(0xFFFFFFFFu, sum, o);
            const float inv = 1.0f / sum;

            const float w1 = val1 ? e1 * inv : 0.0f;
            Wd2[row * COLS + j1] = make_float2(w1, w1);
            if (lane < 16) {
                const float w2 = val2 ? e2 * inv : 0.0f;
                Wd2[row * COLS + j2] = make_float2(w2, w2);
            }
        } else if (tt + 1 < CHAIN) {
            const int idx  = tid - 512;
            const int krow = idx >> 5;        // 0..15
            const int kcol = idx & 31;
            int gr = s0 + ROWS + krow;
            if (gr > S - 1) gr = S - 1;
            const float4* src = in4 + (size_t)gr * D4 + kcol;
            #pragma unroll
            for (int c = 0; c < 8; ++c)
                st[c] = src[32 * c];
        }
        __syncthreads();   // weights ready

        // ===== Phase B (threads 0-511): out = W * F =====
        if (tid < 512) {
            const int a = tid >> 8;     // rows a*8 .. a*8+7
            const int b = tid & 255;    // float4 column

            u64 acc[8][2];
            #pragma unroll
            for (int ii = 0; ii < 8; ++ii) { acc[ii][0] = 0ull; acc[ii][1] = 0ull; }

            #pragma unroll 2
            for (int jp = 0; jp < 24; ++jp) {
                const int jl = jp * 2;
                int sl1 = jl + rot;     if (sl1 >= ROWS) sl1 -= ROWS;
                int sl2 = jl + 1 + rot; if (sl2 >= ROWS) sl2 -= ROWS;
                const ulonglong2 f1 = tileU[sl1 * PITCH4 + b];
                const ulonglong2 f2 = tileU[sl2 * PITCH4 + b];
                #pragma unroll
                for (int ii = 0; ii < 8; ++ii) {
                    const ulonglong2 wp =
                        *reinterpret_cast<const ulonglong2*>(&Wd[(a * 8 + ii) * COLS + jl]);
                    fma2(acc[ii][0], wp.x, f1.x);
                    fma2(acc[ii][1], wp.x, f1.y);
                    fma2(acc[ii][0], wp.y, f2.x);
                    fma2(acc[ii][1], wp.y, f2.y);
                }
            }

            #pragma unroll
            for (int ii = 0; ii < 8; ++ii) {
                const int s = s0 + a * 8 + ii;
                if (s < S) {
                    const float2 lo = *reinterpret_cast<float2*>(&acc[ii][0]);
                    const float2 hi = *reinterpret_cast<float2*>(&acc[ii][1]);
                    out4[(size_t)s * D4 + b] = make_float4(lo.x, lo.y, hi.x, hi.y);
                }
            }
        }
        __syncthreads();   // phase B tile reads done

        // ===== write stashed refresh rows into ring (warps 16-31) =====
        if (tt + 1 < CHAIN) {
            if (tid >= 512) {
                const int idx  = tid - 512;
                const int krow = idx >> 5;
                const int kcol = idx & 31;
                int slot = rot + krow; if (slot >= ROWS) slot -= ROWS;
                float4* dst = tile4 + slot * PITCH4 + kcol;
                #pragma unroll
                for (int c = 0; c < 8; ++c)
                    dst[32 * c] = st[c];
            }
            rot += S_TILE; if (rot >= ROWS) rot -= ROWS;
        }
    }
}

extern "C" void kernel_launch(void* const* d_in, const int* in_sizes, int n_in,
                              void* d_out, int out_size)
{
    (void)n_in; (void)out_size;
    const float* in = (const float*)d_in[0];
    float* out = (float*)d_out;

    const int S = 2048;
    const int B = in_sizes[0] / (S * DCONST);
    const int chains = S / (S_TILE * CHAIN);   // 32

    cudaFuncSetAttribute(future_encoder_kernel,
                         cudaFuncAttributeMaxDynamicSharedMemorySize,
                         SMEM_BYTES);

    dim3 grid(chains, B);
    future_encoder_kernel<<<grid, 1024, SMEM_BYTES>>>(in, out, S);
}

// round 8
// speedup vs baseline: 1.6325x; 1.6325x over previous
#include <cuda_runtime.h>

#define S_TILE   16
#define KF       32
#define ROWS     48            // S_TILE + KF (ring buffer size)
#define CHAIN    4             // s-tiles per CTA
#define DCONST   1024
#define D4       256           // D / 4
#define PITCH4   257           // float4 pitch per row
#define COLS     48
#define NEG_BIG  -1.0e9f
#define NTHREADS 768

#define TILE_F4      (ROWS * PITCH4)
#define RED_OFF      (TILE_F4 * 4)            // 49344
#define RED_SIZE     (8 * S_TILE * COLS)
#define W_OFF        (RED_OFF + RED_SIZE)     // 55488
#define SMEM_FLOATS  (W_OFF + S_TILE * COLS * 2)
#define SMEM_BYTES   (SMEM_FLOATS * 4)        // 228096 B

typedef unsigned long long u64;

__device__ __forceinline__ void fma2(u64& d, u64 a, u64 b) {
    asm("fma.rn.f32x2 %0, %1, %2, %0;" : "+l"(d) : "l"(a), "l"(b));
}
__device__ __forceinline__ float sum2(u64 a) {
    float2 v = *reinterpret_cast<float2*>(&a);
    return v.x + v.y;
}

__global__ __launch_bounds__(NTHREADS, 1)
void future_encoder_kernel(const float* __restrict__ in,
                           float* __restrict__ out,
                           int S)
{
    extern __shared__ float smem[];
    ulonglong2* tileU = reinterpret_cast<ulonglong2*>(smem);
    float4*     tile4 = reinterpret_cast<float4*>(smem);
    float*      red   = smem + RED_OFF;
    u64*        Wd    = reinterpret_cast<u64*>(smem + W_OFF);
    float2*     Wd2   = reinterpret_cast<float2*>(smem + W_OFF);

    const int tid   = threadIdx.x;
    const int chain = blockIdx.x;
    const int bb    = blockIdx.y;
    const int t0    = chain * CHAIN;

    const float4* in4  = reinterpret_cast<const float4*>(in)  + (size_t)bb * S * D4;
    float4*       out4 = reinterpret_cast<float4*>(out)       + (size_t)bb * S * D4;

    // ---- initial load: 48 rows x 256 f4 = 12288 f4, 16 per thread, coalesced ----
    #pragma unroll
    for (int it = 0; it < 16; ++it) {
        const int idx = tid + it * NTHREADS;
        const int r = idx >> 8;
        const int c = idx & 255;
        int gr = t0 * S_TILE + r;
        if (gr > S - 1) gr = S - 1;
        tile4[r * PITCH4 + c] = in4[(size_t)gr * D4 + c];
    }

    int rot = 0;

    for (int tt = 0; tt < CHAIN; ++tt) {
        const int s0 = (t0 + tt) * S_TILE;
        __syncthreads();   // tile (loads / refresh) visible

        // ===== Phase A (24 warps): warp=(d-group g in [0,8), j-third) =====
        // lane: 4 q-rows a,a+4,a+8,a+12 ; 2 j cols third*16 + (lane&7) + {0,8}
        {
            const int w     = tid >> 5;
            const int lane  = tid & 31;
            const int g     = w & 7;          // d-group (128 dims)
            const int third = w >> 3;         // j-third 0..2
            const int a     = lane >> 3;      // 0..3
            const int b     = lane & 7;       // 0..7
            const int base  = g * 32;         // f4 col start

            int qs[4];
            #pragma unroll
            for (int ii = 0; ii < 4; ++ii) {
                int r = a + 4 * ii + rot; if (r >= ROWS) r -= ROWS;
                qs[ii] = r * PITCH4;
            }
            int fs[2];
            #pragma unroll
            for (int jj = 0; jj < 2; ++jj) {
                int r = third * 16 + b + 8 * jj + rot; if (r >= ROWS) r -= ROWS;
                fs[jj] = r * PITCH4;
            }

            u64 acc[4][2];
            #pragma unroll
            for (int ii = 0; ii < 4; ++ii) { acc[ii][0] = 0ull; acc[ii][1] = 0ull; }

            #pragma unroll 8
            for (int step = 0; step < 32; ++step) {
                const int col = base + step;
                ulonglong2 q[4], f[2];
                #pragma unroll
                for (int ii = 0; ii < 4; ++ii) q[ii] = tileU[qs[ii] + col];
                #pragma unroll
                for (int jj = 0; jj < 2; ++jj) f[jj] = tileU[fs[jj] + col];
                #pragma unroll
                for (int ii = 0; ii < 4; ++ii)
                    #pragma unroll
                    for (int jj = 0; jj < 2; ++jj) {
                        fma2(acc[ii][jj], q[ii].x, f[jj].x);
                        fma2(acc[ii][jj], q[ii].y, f[jj].y);
                    }
            }

            float* myred = red + g * (S_TILE * COLS);
            #pragma unroll
            for (int ii = 0; ii < 4; ++ii)
                #pragma unroll
                for (int jj = 0; jj < 2; ++jj)
                    myred[(a + 4 * ii) * COLS + third * 16 + b + 8 * jj] =
                        sum2(acc[ii][jj]);
        }
        __syncthreads();   // red complete

        // ===== reduce + mask + softmax (warps 0-15; warp = query row) =====
        if (tid < 512) {
            const int row  = tid >> 5;
            const int lane = tid & 31;

            float s1 = 0.0f, s2 = 0.0f;
            #pragma unroll
            for (int g = 0; g < 8; ++g)
                s1 += red[g * (S_TILE * COLS) + row * COLS + lane];
            if (lane < 16) {
                #pragma unroll
                for (int g = 0; g < 8; ++g)
                    s2 += red[g * (S_TILE * COLS) + row * COLS + 32 + lane];
            }

            const int j1 = lane;
            const int k1 = j1 - row - 1;
            const bool val1 = (k1 >= 0) && (k1 < KF) && (s0 + j1 < S);
            const float v1 = val1 ? s1 : NEG_BIG;

            const int j2 = 32 + lane;
            const int k2 = j2 - row - 1;
            const bool val2 = (lane < 16) && (k2 >= 0) && (k2 < KF) && (s0 + j2 < S);
            const float v2 = val2 ? s2 : NEG_BIG;

            float m = fmaxf(v1, v2);
            #pragma unroll
            for (int o = 16; o > 0; o >>= 1)
                m = fmaxf(m, __shfl_xor_sync(0xFFFFFFFFu, m, o));

            const float e1 = __expf(v1 - m);
            const float e2 = (lane < 16) ? __expf(v2 - m) : 0.0f;
            float sum = e1 + e2;
            #pragma unroll
            for (int o = 16; o > 0; o >>= 1)
                sum += __shfl_xor_sync(0xFFFFFFFFu, sum, o);
            const float inv = 1.0f / sum;

            const float w1 = val1 ? e1 * inv : 0.0f;
            Wd2[row * COLS + j1] = make_float2(w1, w1);
            if (lane < 16) {
                const float w2 = val2 ? e2 * inv : 0.0f;
                Wd2[row * COLS + j2] = make_float2(w2, w2);
            }
        }
        __syncthreads();   // weights ready

        // ===== Phase B (threads 0-511): out = W * F =====
        if (tid < 512) {
            const int a = tid >> 8;     // rows a*8 .. a*8+7
            const int b = tid & 255;    // float4 column

            u64 acc[8][2];
            #pragma unroll
            for (int ii = 0; ii < 8; ++ii) { acc[ii][0] = 0ull; acc[ii][1] = 0ull; }

            #pragma unroll 4
            for (int jp = 0; jp < 24; ++jp) {
                const int jl = jp * 2;
                int sl1 = jl + rot;     if (sl1 >= ROWS) sl1 -= ROWS;
                int sl2 = jl + 1 + rot; if (sl2 >= ROWS) sl2 -= ROWS;
                const ulonglong2 f1 = tileU[sl1 * PITCH4 + b];
                const ulonglong2 f2 = tileU[sl2 * PITCH4 + b];
                #pragma unroll
                for (int ii = 0; ii < 8; ++ii) {
                    const ulonglong2 wp =
                        *reinterpret_cast<const ulonglong2*>(&Wd[(a * 8 + ii) * COLS + jl]);
                    fma2(acc[ii][0], wp.x, f1.x);
                    fma2(acc[ii][1], wp.x, f1.y);
                    fma2(acc[ii][0], wp.y, f2.x);
                    fma2(acc[ii][1], wp.y, f2.y);
                }
            }

            #pragma unroll
            for (int ii = 0; ii < 8; ++ii) {
                const int s = s0 + a * 8 + ii;
                if (s < S) {
                    const float2 lo = *reinterpret_cast<float2*>(&acc[ii][0]);
                    const float2 hi = *reinterpret_cast<float2*>(&acc[ii][1]);
                    out4[(size_t)s * D4 + b] = make_float4(lo.x, lo.y, hi.x, hi.y);
                }
            }
        }
        __syncthreads();   // phase B tile reads done

        // ===== ring refresh via cp.async (warps 16-23), no register stash =====
        if (tt + 1 < CHAIN) {
            if (tid >= 512) {
                const int idx  = tid - 512;       // 0..255
                const int krow = idx >> 4;        // 0..15
                const int kcol = idx & 15;        // 16 f4 per thread, stride 16
                int slot = rot + krow; if (slot >= ROWS) slot -= ROWS;
                int gr = s0 + ROWS + krow;
                if (gr > S - 1) gr = S - 1;
                const float4* src = in4 + (size_t)gr * D4 + kcol;
                unsigned dst = (unsigned)__cvta_generic_to_shared(
                                   tile4 + slot * PITCH4 + kcol);
                #pragma unroll
                for (int c = 0; c < 16; ++c) {
                    asm volatile("cp.async.cg.shared.global [%0], [%1], 16;\n"
                                 :: "r"(dst + c * 16 * 16),
                                    "l"(src + c * 16));
                }
                asm volatile("cp.async.commit_group;\n");
                asm volatile("cp.async.wait_group 0;\n");
            }
            rot += S_TILE; if (rot >= ROWS) rot -= ROWS;
        }
    }
}

extern "C" void kernel_launch(void* const* d_in, const int* in_sizes, int n_in,
                              void* d_out, int out_size)
{
    (void)n_in; (void)out_size;
    const float* in = (const float*)d_in[0];
    float* out = (float*)d_out;

    const int S = 2048;
    const int B = in_sizes[0] / (S * DCONST);
    const int chains = S / (S_TILE * CHAIN);   // 32

    cudaFuncSetAttribute(future_encoder_kernel,
                         cudaFuncAttributeMaxDynamicSharedMemorySize,
                         SMEM_BYTES);

    dim3 grid(chains, B);
    future_encoder_kernel<<<grid, NTHREADS, SMEM_BYTES>>>(in, out, S);
}

// round 9
// speedup vs baseline: 1.6333x; 1.0005x over previous
#include <cuda_runtime.h>

#define S_TILE   16
#define KF       32
#define ROWS     48            // S_TILE + KF (ring buffer size)
#define CHAIN    4             // s-tiles per CTA
#define DCONST   1024
#define D4       256           // D / 4
#define PITCH4   257           // float4 pitch per row
#define COLS     48
#define NEG_BIG  -1.0e9f
#define NTHREADS 768

#define TILE_F4      (ROWS * PITCH4)
#define RED_OFF      (TILE_F4 * 4)            // 49344
#define RED_SIZE     (8 * S_TILE * COLS)
#define W_OFF        (RED_OFF + RED_SIZE)     // 55488
#define SMEM_FLOATS  (W_OFF + S_TILE * COLS * 2)
#define SMEM_BYTES   (SMEM_FLOATS * 4)        // 228096 B

typedef unsigned long long u64;

__device__ __forceinline__ void fma2(u64& d, u64 a, u64 b) {
    asm("fma.rn.f32x2 %0, %1, %2, %0;" : "+l"(d) : "l"(a), "l"(b));
}
__device__ __forceinline__ float sum2(u64 a) {
    float2 v = *reinterpret_cast<float2*>(&a);
    return v.x + v.y;
}

__global__ __launch_bounds__(NTHREADS, 1)
void future_encoder_kernel(const float* __restrict__ in,
                           float* __restrict__ out,
                           int S)
{
    extern __shared__ float smem[];
    ulonglong2* tileU = reinterpret_cast<ulonglong2*>(smem);
    float4*     tile4 = reinterpret_cast<float4*>(smem);
    float*      red   = smem + RED_OFF;
    u64*        Wd    = reinterpret_cast<u64*>(smem + W_OFF);
    float2*     Wd2   = reinterpret_cast<float2*>(smem + W_OFF);

    const int tid   = threadIdx.x;
    const int chain = blockIdx.x;
    const int bb    = blockIdx.y;
    const int t0    = chain * CHAIN;

    const float4* in4  = reinterpret_cast<const float4*>(in)  + (size_t)bb * S * D4;
    float4*       out4 = reinterpret_cast<float4*>(out)       + (size_t)bb * S * D4;

    // ---- initial load: 48 rows x 256 f4 = 12288 f4, 16 per thread, coalesced ----
    #pragma unroll
    for (int it = 0; it < 16; ++it) {
        const int idx = tid + it * NTHREADS;
        const int r = idx >> 8;
        const int c = idx & 255;
        int gr = t0 * S_TILE + r;
        if (gr > S - 1) gr = S - 1;
        tile4[r * PITCH4 + c] = in4[(size_t)gr * D4 + c];
    }

    int rot = 0;

    for (int tt = 0; tt < CHAIN; ++tt) {
        const int s0 = (t0 + tt) * S_TILE;
        __syncthreads();   // tile (loads / refresh) visible

        // ===== Phase A (24 warps): warp=(d-group g in [0,8), j-third) =====
        // lane: 4 q-rows a,a+4,a+8,a+12 ; 2 j cols third*16 + (lane&7) + {0,8}
        {
            const int w     = tid >> 5;
            const int lane  = tid & 31;
            const int g     = w & 7;          // d-group (128 dims)
            const int third = w >> 3;         // j-third 0..2
            const int a     = lane >> 3;      // 0..3
            const int b     = lane & 7;       // 0..7
            const int base  = g * 32;         // f4 col start

            int qs[4];
            #pragma unroll
            for (int ii = 0; ii < 4; ++ii) {
                int r = a + 4 * ii + rot; if (r >= ROWS) r -= ROWS;
                qs[ii] = r * PITCH4;
            }
            int fs[2];
            #pragma unroll
            for (int jj = 0; jj < 2; ++jj) {
                int r = third * 16 + b + 8 * jj + rot; if (r >= ROWS) r -= ROWS;
                fs[jj] = r * PITCH4;
            }

            u64 acc[4][2];
            #pragma unroll
            for (int ii = 0; ii < 4; ++ii) { acc[ii][0] = 0ull; acc[ii][1] = 0ull; }

            #pragma unroll 8
            for (int step = 0; step < 32; ++step) {
                const int col = base + step;
                ulonglong2 q[4], f[2];
                #pragma unroll
                for (int ii = 0; ii < 4; ++ii) q[ii] = tileU[qs[ii] + col];
                #pragma unroll
                for (int jj = 0; jj < 2; ++jj) f[jj] = tileU[fs[jj] + col];
                #pragma unroll
                for (int ii = 0; ii < 4; ++ii)
                    #pragma unroll
                    for (int jj = 0; jj < 2; ++jj) {
                        fma2(acc[ii][jj], q[ii].x, f[jj].x);
                        fma2(acc[ii][jj], q[ii].y, f[jj].y);
                    }
            }

            float* myred = red + g * (S_TILE * COLS);
            #pragma unroll
            for (int ii = 0; ii < 4; ++ii)
                #pragma unroll
                for (int jj = 0; jj < 2; ++jj)
                    myred[(a + 4 * ii) * COLS + third * 16 + b + 8 * jj] =
                        sum2(acc[ii][jj]);
        }
        __syncthreads();   // red complete

        // ===== reduce + mask + softmax (warps 0-15; warp = query row) =====
        if (tid < 512) {
            const int row  = tid >> 5;
            const int lane = tid & 31;

            float s1 = 0.0f, s2 = 0.0f;
            #pragma unroll
            for (int g = 0; g < 8; ++g)
                s1 += red[g * (S_TILE * COLS) + row * COLS + lane];
            if (lane < 16) {
                #pragma unroll
                for (int g = 0; g < 8; ++g)
                    s2 += red[g * (S_TILE * COLS) + row * COLS + 32 + lane];
            }

            const int j1 = lane;
            const int k1 = j1 - row - 1;
            const bool val1 = (k1 >= 0) && (k1 < KF) && (s0 + j1 < S);
            const float v1 = val1 ? s1 : NEG_BIG;

            const int j2 = 32 + lane;
            const int k2 = j2 - row - 1;
            const bool val2 = (lane < 16) && (k2 >= 0) && (k2 < KF) && (s0 + j2 < S);
            const float v2 = val2 ? s2 : NEG_BIG;

            float m = fmaxf(v1, v2);
            #pragma unroll
            for (int o = 16; o > 0; o >>= 1)
                m = fmaxf(m, __shfl_xor_sync(0xFFFFFFFFu, m, o));

            const float e1 = __expf(v1 - m);
            const float e2 = (lane < 16) ? __expf(v2 - m) : 0.0f;
            float sum = e1 + e2;
            #pragma unroll
            for (int o = 16; o > 0; o >>= 1)
                sum += __shfl_xor_sync(0xFFFFFFFFu, sum, o);
            const float inv = 1.0f / sum;

            const float w1 = val1 ? e1 * inv : 0.0f;
            Wd2[row * COLS + j1] = make_float2(w1, w1);
            if (lane < 16) {
                const float w2 = val2 ? e2 * inv : 0.0f;
                Wd2[row * COLS + j2] = make_float2(w2, w2);
            }
        }
        __syncthreads();   // weights ready

        // ===== Phase B (threads 0-511): out = W * F =====
        if (tid < 512) {
            const int a = tid >> 8;     // rows a*8 .. a*8+7
            const int b = tid & 255;    // float4 column

            u64 acc[8][2];
            #pragma unroll
            for (int ii = 0; ii < 8; ++ii) { acc[ii][0] = 0ull; acc[ii][1] = 0ull; }

            #pragma unroll 4
            for (int jp = 0; jp < 24; ++jp) {
                const int jl = jp * 2;
                int sl1 = jl + rot;     if (sl1 >= ROWS) sl1 -= ROWS;
                int sl2 = jl + 1 + rot; if (sl2 >= ROWS) sl2 -= ROWS;
                const ulonglong2 f1 = tileU[sl1 * PITCH4 + b];
                const ulonglong2 f2 = tileU[sl2 * PITCH4 + b];
                #pragma unroll
                for (int ii = 0; ii < 8; ++ii) {
                    const ulonglong2 wp =
                        *reinterpret_cast<const ulonglong2*>(&Wd[(a * 8 + ii) * COLS + jl]);
                    fma2(acc[ii][0], wp.x, f1.x);
                    fma2(acc[ii][1], wp.x, f1.y);
                    fma2(acc[ii][0], wp.y, f2.x);
                    fma2(acc[ii][1], wp.y, f2.y);
                }
            }

            #pragma unroll
            for (int ii = 0; ii < 8; ++ii) {
                const int s = s0 + a * 8 + ii;
                if (s < S) {
                    const float2 lo = *reinterpret_cast<float2*>(&acc[ii][0]);
                    const float2 hi = *reinterpret_cast<float2*>(&acc[ii][1]);
                    out4[(size_t)s * D4 + b] = make_float4(lo.x, lo.y, hi.x, hi.y);
                }
            }
        }
        __syncthreads();   // phase B tile reads done

        // ===== ring refresh via cp.async (warps 16-23), no register stash =====
        if (tt + 1 < CHAIN) {
            if (tid >= 512) {
                const int idx  = tid - 512;       // 0..255
                const int krow = idx >> 4;        // 0..15
                const int kcol = idx & 15;        // 16 f4 per thread, stride 16
                int slot = rot + krow; if (slot >= ROWS) slot -= ROWS;
                int gr = s0 + ROWS + krow;
                if (gr > S - 1) gr = S - 1;
                const float4* src = in4 + (size_t)gr * D4 + kcol;
                unsigned dst = (unsigned)__cvta_generic_to_shared(
                                   tile4 + slot * PITCH4 + kcol);
                #pragma unroll
                for (int c = 0; c < 16; ++c) {
                    asm volatile("cp.async.cg.shared.global [%0], [%1], 16;\n"
                                 :: "r"(dst + c * 16 * 16),
                                    "l"(src + c * 16));
                }
                asm volatile("cp.async.commit_group;\n");
                asm volatile("cp.async.wait_group 0;\n");
            }
            rot += S_TILE; if (rot >= ROWS) rot -= ROWS;
        }
    }
}

extern "C" void kernel_launch(void* const* d_in, const int* in_sizes, int n_in,
                              void* d_out, int out_size)
{
    (void)n_in; (void)out_size;
    const float* in = (const float*)d_in[0];
    float* out = (float*)d_out;

    const int S = 2048;
    const int B = in_sizes[0] / (S * DCONST);
    const int chains = S / (S_TILE * CHAIN);   // 32

    cudaFuncSetAttribute(future_encoder_kernel,
                         cudaFuncAttributeMaxDynamicSharedMemorySize,
                         SMEM_BYTES);

    dim3 grid(chains, B);
    future_encoder_kernel<<<grid, NTHREADS, SMEM_BYTES>>>(in, out, S);
}

// round 11
// speedup vs baseline: 1.8069x; 1.1063x over previous
#include <cuda_runtime.h>

#define S_TILE   16
#define KF       32
#define ROWS     48            // S_TILE + KF (ring buffer size)
#define CHAIN    4             // s-tiles per CTA
#define DCONST   1024
#define D4       256           // D / 4
#define PITCH4   257           // float4 pitch per row
#define COLS     48
#define WPITCH   50            // weight-row pitch in u64 (even -> 16B aligned)
#define NEG_BIG  -1.0e9f

// weight row r starts at WROW(r) u64: +2 stagger for upper half breaks the
// 16*WPITCH = 0 mod 32 bank collision between rows ii and ii+8.
#define WROW(r)  ((r) * WPITCH + (((r) >> 3) << 1))

#define TILE_F4      (ROWS * PITCH4)
#define RED_OFF      (TILE_F4 * 4)            // 49344
#define RED_SIZE     (8 * S_TILE * COLS)
#define W_OFF        (RED_OFF + RED_SIZE)     // 55488 (byte 221952: 16B aligned)
#define W_U64        800                      // WROW(15)+48 = 799 -> 800
#define SMEM_FLOATS  (W_OFF + W_U64 * 2)
#define SMEM_BYTES   (SMEM_FLOATS * 4)        // 228352 B

typedef unsigned long long u64;

__device__ __forceinline__ void fma2(u64& d, u64 a, u64 b) {
    asm("fma.rn.f32x2 %0, %1, %2, %0;" : "+l"(d) : "l"(a), "l"(b));
}
__device__ __forceinline__ float sum2(u64 a) {
    float2 v = *reinterpret_cast<float2*>(&a);
    return v.x + v.y;
}

__global__ __launch_bounds__(512, 1)
void future_encoder_kernel(const float* __restrict__ in,
                           float* __restrict__ out,
                           int S)
{
    extern __shared__ float smem[];
    ulonglong2* tileU = reinterpret_cast<ulonglong2*>(smem);
    float4*     tile4 = reinterpret_cast<float4*>(smem);
    float*      red   = smem + RED_OFF;
    u64*        Wd    = reinterpret_cast<u64*>(smem + W_OFF);
    float2*     Wd2   = reinterpret_cast<float2*>(smem + W_OFF);

    const int tid   = threadIdx.x;
    const int chain = blockIdx.x;
    const int bb    = blockIdx.y;
    const int t0    = chain * CHAIN;

    const float4* in4  = reinterpret_cast<const float4*>(in)  + (size_t)bb * S * D4;
    float4*       out4 = reinterpret_cast<float4*>(out)       + (size_t)bb * S * D4;

    // ---- initial load: 48 rows into slots 0..47 ----
    {
        const int half = tid >> 8;
        const int col  = tid & 255;
        #pragma unroll 4
        for (int it = 0; it < 24; ++it) {
            const int r = it * 2 + half;
            int gr = t0 * S_TILE + r;
            if (gr > S - 1) gr = S - 1;
            tile4[r * PITCH4 + col] = in4[(size_t)gr * D4 + col];
        }
    }

    int rot = 0;

    for (int tt = 0; tt < CHAIN; ++tt) {
        const int s0 = (t0 + tt) * S_TILE;
        __syncthreads();   // tile (loads / refresh) visible

        // ===== Phase A (R3 shape): warp = (d-group g, j-half) =====
        {
            const int w    = tid >> 5;
            const int lane = tid & 31;
            const int g    = w >> 1;          // d-group 0..7 (128 dims)
            const int j0   = (w & 1) * 24;    // j half
            const int a    = lane >> 3;       // q rows a, a+4, a+8, a+12
            const int b    = lane & 7;        // f cols j0+b, +8, +16

            int qs[4], fs[3];
            #pragma unroll
            for (int ii = 0; ii < 4; ++ii) {
                int r = a + 4 * ii + rot; if (r >= ROWS) r -= ROWS;
                qs[ii] = r * PITCH4;
            }
            #pragma unroll
            for (int jj = 0; jj < 3; ++jj) {
                int r = j0 + b + 8 * jj + rot; if (r >= ROWS) r -= ROWS;
                fs[jj] = r * PITCH4;
            }

            u64 acc[4][3];
            #pragma unroll
            for (int ii = 0; ii < 4; ++ii)
                #pragma unroll
                for (int jj = 0; jj < 3; ++jj)
                    acc[ii][jj] = 0ull;

            const int base = g * 32;
            #pragma unroll 4
            for (int step = 0; step < 32; ++step) {
                const int col = base + step;
                ulonglong2 q[4], f[3];
                #pragma unroll
                for (int ii = 0; ii < 4; ++ii)
                    q[ii] = tileU[qs[ii] + col];
                #pragma unroll
                for (int jj = 0; jj < 3; ++jj)
                    f[jj] = tileU[fs[jj] + col];
                #pragma unroll
                for (int ii = 0; ii < 4; ++ii)
                    #pragma unroll
                    for (int jj = 0; jj < 3; ++jj) {
                        fma2(acc[ii][jj], q[ii].x, f[jj].x);
                        fma2(acc[ii][jj], q[ii].y, f[jj].y);
                    }
            }

            float* myred = red + g * (S_TILE * COLS);
            #pragma unroll
            for (int ii = 0; ii < 4; ++ii)
                #pragma unroll
                for (int jj = 0; jj < 3; ++jj)
                    myred[(a + 4 * ii) * COLS + (j0 + b + 8 * jj)] = sum2(acc[ii][jj]);
        }

        // ---- early refresh LDG: next tile's 16 rows -> registers ----
        float4 st[8];
        const bool do_refresh = (tt + 1 < CHAIN);
        if (do_refresh) {
            const int krow = tid >> 5;            // 0..15
            const int kcol = tid & 31;
            int gr = s0 + ROWS + krow;
            if (gr > S - 1) gr = S - 1;
            const float4* src = in4 + (size_t)gr * D4 + kcol;
            #pragma unroll
            for (int c = 0; c < 8; ++c)
                st[c] = src[32 * c];
        }
        __syncthreads();   // red complete

        // ---- reduce over d-groups + mask + softmax (warp = query row) ----
        {
            const int row  = tid >> 5;
            const int lane = tid & 31;

            float s1 = 0.0f, s2 = 0.0f;
            #pragma unroll
            for (int g = 0; g < 8; ++g)
                s1 += red[g * (S_TILE * COLS) + row * COLS + lane];
            if (lane < 16) {
                #pragma unroll
                for (int g = 0; g < 8; ++g)
                    s2 += red[g * (S_TILE * COLS) + row * COLS + 32 + lane];
            }

            const int j1 = lane;
            const int k1 = j1 - row - 1;
            const bool val1 = (k1 >= 0) && (k1 < KF) && (s0 + j1 < S);
            const float v1 = val1 ? s1 : NEG_BIG;

            const int j2 = 32 + lane;
            const int k2 = j2 - row - 1;
            const bool val2 = (lane < 16) && (k2 >= 0) && (k2 < KF) && (s0 + j2 < S);
            const float v2 = val2 ? s2 : NEG_BIG;

            float m = fmaxf(v1, v2);
            #pragma unroll
            for (int o = 16; o > 0; o >>= 1)
                m = fmaxf(m, __shfl_xor_sync(0xFFFFFFFFu, m, o));

            const float e1 = __expf(v1 - m);
            const float e2 = (lane < 16) ? __expf(v2 - m) : 0.0f;
            float sum = e1 + e2;
            #pragma unroll
            for (int o = 16; o > 0; o >>= 1)
                sum += __shfl_xor_sync(0xFFFFFFFFu, sum, o);
            const float inv = 1.0f / sum;

            const int wbase = WROW(row);
            const float w1 = val1 ? e1 * inv : 0.0f;
            Wd2[wbase + j1] = make_float2(w1, w1);
            if (lane < 16) {
                const float w2 = val2 ? e2 * inv : 0.0f;
                Wd2[wbase + j2] = make_float2(w2, w2);
            }
        }
        __syncthreads();   // weights ready

        // ===== Phase B: warp = 16 cols x 2 row-halves (f-loads 2 wf, not 4) =====
        {
            const int w    = tid >> 5;      // 0..15
            const int lane = tid & 31;
            const int cl   = lane & 15;     // col within warp group
            const int h    = lane >> 4;     // row half 0/1
            const int b    = w * 16 + cl;   // f4 column 0..255

            int wrow[8];
            #pragma unroll
            for (int ii = 0; ii < 8; ++ii)
                wrow[ii] = WROW(h * 8 + ii);

            u64 acc[8][2];
            #pragma unroll
            for (int ii = 0; ii < 8; ++ii) { acc[ii][0] = 0ull; acc[ii][1] = 0ull; }

            #pragma unroll 2
            for (int jp = 0; jp < 24; ++jp) {
                const int jl = jp * 2;
                int sl1 = jl + rot;     if (sl1 >= ROWS) sl1 -= ROWS;
                int sl2 = jl + 1 + rot; if (sl2 >= ROWS) sl2 -= ROWS;
                const ulonglong2 f1 = tileU[sl1 * PITCH4 + b];  // 16 cols x2 dup: 2 wf
                const ulonglong2 f2 = tileU[sl2 * PITCH4 + b];
                #pragma unroll
                for (int ii = 0; ii < 8; ++ii) {
                    const ulonglong2 wp =
                        *reinterpret_cast<const ulonglong2*>(&Wd[wrow[ii] + jl]);
                    fma2(acc[ii][0], wp.x, f1.x);
                    fma2(acc[ii][1], wp.x, f1.y);
                    fma2(acc[ii][0], wp.y, f2.x);
                    fma2(acc[ii][1], wp.y, f2.y);
                }
            }

            #pragma unroll
            for (int ii = 0; ii < 8; ++ii) {
                const int s = s0 + h * 8 + ii;
                if (s < S) {
                    const float2 lo = *reinterpret_cast<float2*>(&acc[ii][0]);
                    const float2 hi = *reinterpret_cast<float2*>(&acc[ii][1]);
                    out4[(size_t)s * D4 + b] = make_float4(lo.x, lo.y, hi.x, hi.y);
                }
            }
        }

        // ---- write stashed refresh rows into ring ----
        if (do_refresh) {
            __syncthreads();   // phase B tile reads done before overwrite
            const int krow = tid >> 5;
            const int kcol = tid & 31;
            int slot = rot + krow; if (slot >= ROWS) slot -= ROWS;
            float4* dst = tile4 + slot * PITCH4 + kcol;
            #pragma unroll
            for (int c = 0; c < 8; ++c)
                dst[32 * c] = st[c];
            rot += S_TILE; if (rot >= ROWS) rot -= ROWS;
        }
    }
}

extern "C" void kernel_launch(void* const* d_in, const int* in_sizes, int n_in,
                              void* d_out, int out_size)
{
    (void)n_in; (void)out_size;
    const float* in = (const float*)d_in[0];
    float* out = (float*)d_out;

    const int S = 2048;
    const int B = in_sizes[0] / (S * DCONST);
    const int chains = S / (S_TILE * CHAIN);   // 32

    cudaFuncSetAttribute(future_encoder_kernel,
                         cudaFuncAttributeMaxDynamicSharedMemorySize,
                         SMEM_BYTES);

    dim3 grid(chains, B);
    future_encoder_kernel<<<grid, 512, SMEM_BYTES>>>(in, out, S);
}